// round 1
// baseline (speedup 1.0000x reference)
#include <cuda_runtime.h>
#include <math_constants.h>

// Problem shape (fixed by the dataset)
constexpr int Bn = 4;
constexpr int Tn = 4096;
constexpr int Dn = 1024;
constexpr int Hn = 64;
constexpr float SCALE = 0.125f;  // 1/sqrt(64)

// ---------------- scratch (__device__ globals: the sanctioned scratch path) ----
__device__ float g_Q[(size_t)Bn * Tn * Hn];          // 4 MB
__device__ float g_K[(size_t)Bn * Tn * Hn];          // 4 MB
__device__ float g_V[(size_t)Bn * Tn * Dn];          // 64 MB
__device__ float g_S[(size_t)Bn * Tn * Tn];          // 256 MB raw scaled scores
__device__ float g_m[Bn * Tn];                        // row max
__device__ float g_l[Bn * Tn];                        // row sum-exp

// =============================================================================
// Kernel 1: C[M,N] = A[M,K] * W[N,K]^T   (all row-major). 128x128x8 tile,
// 8x8 per-thread microtile, 256 threads. N may be < BN (guarded).
// =============================================================================
template <int BM, int BN, int BK, int TM, int TN>
__global__ __launch_bounds__(256) void sgemm_tn(const float* __restrict__ A,
                                                const float* __restrict__ W,
                                                float* __restrict__ C,
                                                int M, int N, int K) {
    __shared__ __align__(16) float As[BK][BM];
    __shared__ __align__(16) float Ws[BK][BN];
    const int tid  = threadIdx.x;
    const int bm   = blockIdx.x * BM;
    const int bn   = blockIdx.y * BN;
    const int tcol = tid % (BN / TN);   // 16
    const int trow = tid / (BN / TN);   // 16
    const int a_r  = tid / (BK / 4);    // 0..127
    const int a_c  = (tid % (BK / 4)) * 4;

    const float* Aptr = A + (size_t)(bm + a_r) * K + a_c;
    const float* Wptr = W + (size_t)(bn + a_r) * K + a_c;
    const bool wvalid = (bn + a_r) < N;

    float acc[TM][TN] = {};

    for (int k0 = 0; k0 < K; k0 += BK) {
        float4 av = *(const float4*)(Aptr + k0);
        float4 wv = make_float4(0.f, 0.f, 0.f, 0.f);
        if (wvalid) wv = *(const float4*)(Wptr + k0);
        As[a_c + 0][a_r] = av.x;
        As[a_c + 1][a_r] = av.y;
        As[a_c + 2][a_r] = av.z;
        As[a_c + 3][a_r] = av.w;
        Ws[a_c + 0][a_r] = wv.x;
        Ws[a_c + 1][a_r] = wv.y;
        Ws[a_c + 2][a_r] = wv.z;
        Ws[a_c + 3][a_r] = wv.w;
        __syncthreads();
#pragma unroll
        for (int kk = 0; kk < BK; kk++) {
            float ra[TM], rb[TN];
            *(float4*)&ra[0] = *(const float4*)&As[kk][trow * TM];
            *(float4*)&ra[4] = *(const float4*)&As[kk][trow * TM + 4];
            *(float4*)&rb[0] = *(const float4*)&Ws[kk][tcol * TN];
            *(float4*)&rb[4] = *(const float4*)&Ws[kk][tcol * TN + 4];
#pragma unroll
            for (int i = 0; i < TM; i++)
#pragma unroll
                for (int j = 0; j < TN; j++) acc[i][j] += ra[i] * rb[j];
        }
        __syncthreads();
    }

#pragma unroll
    for (int i = 0; i < TM; i++) {
        const int r = bm + trow * TM + i;
#pragma unroll
        for (int j = 0; j < TN; j += 4) {
            const int c = bn + tcol * TN + j;
            if (c < N) {
                *(float4*)(C + (size_t)r * N + c) =
                    make_float4(acc[i][j], acc[i][j + 1], acc[i][j + 2], acc[i][j + 3]);
            }
        }
    }
}

// =============================================================================
// Kernel 2: raw scaled scores (causal) into g_S + per-row online (m, l).
// One block = (batch, 64-query row tile). 256 threads, 4x4 microtile over a
// 64x64 score tile; sequential loop over key tiles up to the diagonal.
// =============================================================================
__global__ __launch_bounds__(256) void attn_scores_kernel() {
    const int b  = blockIdx.y;
    const int rt = (int)gridDim.x - 1 - (int)blockIdx.x;  // heavy tiles first
    const int i0 = rt * 64;
    const int tid  = threadIdx.x;
    const int tcol = tid & 15;
    const int trow = tid >> 4;

    const float* Qb = g_Q + (size_t)b * Tn * Hn;
    const float* Kb = g_K + (size_t)b * Tn * Hn;
    float*       Sb = g_S + (size_t)b * Tn * Tn;

    __shared__ float Qs[64][Hn + 1];
    __shared__ float Ks[64][Hn + 1];

    // load Q tile (4 threads per row, 16 h each)
    {
        const int r  = tid >> 2;
        const int h0 = (tid & 3) * 16;
        const float* src = Qb + (size_t)(i0 + r) * Hn + h0;
#pragma unroll
        for (int u = 0; u < 4; u++) {
            float4 v = *(const float4*)(src + u * 4);
            Qs[r][h0 + u * 4 + 0] = v.x;
            Qs[r][h0 + u * 4 + 1] = v.y;
            Qs[r][h0 + u * 4 + 2] = v.z;
            Qs[r][h0 + u * 4 + 3] = v.w;
        }
    }

    float run_m[4], run_l[4];
#pragma unroll
    for (int ii = 0; ii < 4; ii++) { run_m[ii] = -CUDART_INF_F; run_l[ii] = 0.f; }

    for (int jt = 0; jt <= rt; jt++) {
        const int j0 = jt * 64;
        __syncthreads();  // Ks safe to overwrite (also covers Qs readiness on iter 0)
        {
            const int r  = tid >> 2;
            const int h0 = (tid & 3) * 16;
            const float* src = Kb + (size_t)(j0 + r) * Hn + h0;
#pragma unroll
            for (int u = 0; u < 4; u++) {
                float4 v = *(const float4*)(src + u * 4);
                Ks[r][h0 + u * 4 + 0] = v.x;
                Ks[r][h0 + u * 4 + 1] = v.y;
                Ks[r][h0 + u * 4 + 2] = v.z;
                Ks[r][h0 + u * 4 + 3] = v.w;
            }
        }
        __syncthreads();

        float s[4][4] = {};
#pragma unroll 8
        for (int h = 0; h < Hn; h++) {
            float qa[4], kb[4];
#pragma unroll
            for (int ii = 0; ii < 4; ii++) qa[ii] = Qs[trow * 4 + ii][h];
#pragma unroll
            for (int jj = 0; jj < 4; jj++) kb[jj] = Ks[tcol * 4 + jj][h];
#pragma unroll
            for (int ii = 0; ii < 4; ii++)
#pragma unroll
                for (int jj = 0; jj < 4; jj++) s[ii][jj] += qa[ii] * kb[jj];
        }

        const bool diag = (jt == rt);
#pragma unroll
        for (int ii = 0; ii < 4; ii++) {
            const int gi = i0 + trow * 4 + ii;
            float v[4];
#pragma unroll
            for (int jj = 0; jj < 4; jj++) {
                const int gj = j0 + tcol * 4 + jj;
                v[jj] = s[ii][jj] * SCALE;
                if (diag && gj > gi) v[jj] = -CUDART_INF_F;
            }
            *(float4*)(Sb + (size_t)gi * Tn + j0 + tcol * 4) =
                make_float4(v[0], v[1], v[2], v[3]);

            // online max / sum-exp across the 16 lanes sharing this row
            float mx = fmaxf(fmaxf(v[0], v[1]), fmaxf(v[2], v[3]));
#pragma unroll
            for (int o = 8; o; o >>= 1)
                mx = fmaxf(mx, __shfl_xor_sync(0xffffffffu, mx, o));
            const float nm = fmaxf(run_m[ii], mx);
            float ps = __expf(v[0] - nm) + __expf(v[1] - nm) +
                       __expf(v[2] - nm) + __expf(v[3] - nm);
#pragma unroll
            for (int o = 8; o; o >>= 1) ps += __shfl_xor_sync(0xffffffffu, ps, o);
            run_l[ii] = run_l[ii] * __expf(run_m[ii] - nm) + ps;
            run_m[ii] = nm;
        }
    }

    if (tcol == 0) {
#pragma unroll
        for (int ii = 0; ii < 4; ii++) {
            const int gi = i0 + trow * 4 + ii;
            g_m[b * Tn + gi] = run_m[ii];
            g_l[b * Tn + gi] = run_l[ii];
        }
    }
}

// =============================================================================
// Kernel 3: O = softmax(S) @ V, normalization applied on the fly while staging
// the S tile into smem. Causal extent per row tile (kEnd = i0+128).
// 128x128x16 tiles, 8x8 microtile, 256 threads.
// =============================================================================
__global__ __launch_bounds__(256) void pv_kernel(float* __restrict__ Out) {
    const int b  = blockIdx.z;
    const int rt = (int)gridDim.x - 1 - (int)blockIdx.x;  // heavy tiles first
    const int i0 = rt * 128;
    const int n0 = blockIdx.y * 128;
    const int tid  = threadIdx.x;
    const int tcol = tid & 15;
    const int trow = tid >> 4;

    const float* Sb = g_S + (size_t)b * Tn * Tn;
    const float* Vb = g_V + (size_t)b * Tn * Dn;
    float*       Ob = Out + (size_t)b * Tn * Dn;

    __shared__ __align__(16) float Ps[16][128];  // [k][m]  (normalized probs)
    __shared__ __align__(16) float Vs[16][128];  // [k][n]
    __shared__ float s_m[128];
    __shared__ float s_li[128];

    if (tid < 128) {
        s_m[tid]  = g_m[b * Tn + i0 + tid];
        s_li[tid] = 1.0f / g_l[b * Tn + i0 + tid];
    }
    __syncthreads();

    float acc[8][8] = {};
    const int kEnd = i0 + 128;

    for (int k0 = 0; k0 < kEnd; k0 += 16) {
        // ---- stage S tile with softmax transform + causal mask ----
#pragma unroll
        for (int t = 0; t < 2; t++) {
            const int idx = tid * 2 + t;
            const int r   = idx >> 2;         // 0..127
            const int c4  = (idx & 3) * 4;    // 0,4,8,12
            const float4 sv = *(const float4*)(Sb + (size_t)(i0 + r) * Tn + k0 + c4);
            const int gi = i0 + r;
            const float mr = s_m[r], lr = s_li[r];
            float p[4];
            p[0] = (k0 + c4 + 0 <= gi) ? __expf(sv.x - mr) * lr : 0.f;
            p[1] = (k0 + c4 + 1 <= gi) ? __expf(sv.y - mr) * lr : 0.f;
            p[2] = (k0 + c4 + 2 <= gi) ? __expf(sv.z - mr) * lr : 0.f;
            p[3] = (k0 + c4 + 3 <= gi) ? __expf(sv.w - mr) * lr : 0.f;
            Ps[c4 + 0][r] = p[0];
            Ps[c4 + 1][r] = p[1];
            Ps[c4 + 2][r] = p[2];
            Ps[c4 + 3][r] = p[3];
        }
        // ---- stage V tile ----
#pragma unroll
        for (int t = 0; t < 2; t++) {
            const int idx = tid + t * 256;
            const int kr  = idx >> 5;
            const int c4  = (idx & 31) * 4;
            *(float4*)&Vs[kr][c4] =
                *(const float4*)(Vb + (size_t)(k0 + kr) * Dn + n0 + c4);
        }
        __syncthreads();

#pragma unroll
        for (int kk = 0; kk < 16; kk++) {
            float ra[8], rb[8];
            *(float4*)&ra[0] = *(const float4*)&Ps[kk][trow * 8];
            *(float4*)&ra[4] = *(const float4*)&Ps[kk][trow * 8 + 4];
            *(float4*)&rb[0] = *(const float4*)&Vs[kk][tcol * 8];
            *(float4*)&rb[4] = *(const float4*)&Vs[kk][tcol * 8 + 4];
#pragma unroll
            for (int i = 0; i < 8; i++)
#pragma unroll
                for (int j = 0; j < 8; j++) acc[i][j] += ra[i] * rb[j];
        }
        __syncthreads();
    }

#pragma unroll
    for (int i = 0; i < 8; i++) {
        const int r = i0 + trow * 8 + i;
        float* dst = Ob + (size_t)r * Dn + n0 + tcol * 8;
        *(float4*)(dst + 0) = make_float4(acc[i][0], acc[i][1], acc[i][2], acc[i][3]);
        *(float4*)(dst + 4) = make_float4(acc[i][4], acc[i][5], acc[i][6], acc[i][7]);
    }
}

// =============================================================================
extern "C" void kernel_launch(void* const* d_in, const int* in_sizes, int n_in,
                              void* d_out, int out_size) {
    const float* x  = (const float*)d_in[0];
    const float* Wk = (const float*)d_in[1];
    const float* Wq = (const float*)d_in[2];
    const float* Wv = (const float*)d_in[3];
    float* out = (float*)d_out;

    void *pQ, *pK, *pV;
    cudaGetSymbolAddress(&pQ, g_Q);
    cudaGetSymbolAddress(&pK, g_K);
    cudaGetSymbolAddress(&pV, g_V);

    const int M = Bn * Tn;  // 16384

    // Projections
    sgemm_tn<128, 128, 8, 8, 8><<<dim3(M / 128, 1), 256>>>(x, Wq, (float*)pQ, M, Hn, Dn);
    sgemm_tn<128, 128, 8, 8, 8><<<dim3(M / 128, 1), 256>>>(x, Wk, (float*)pK, M, Hn, Dn);
    sgemm_tn<128, 128, 8, 8, 8><<<dim3(M / 128, Dn / 128), 256>>>(x, Wv, (float*)pV, M, Dn, Dn);

    // Scores + row stats
    attn_scores_kernel<<<dim3(Tn / 64, Bn), 256>>>();

    // softmax-on-the-fly P @ V
    pv_kernel<<<dim3(Tn / 128, Dn / 128, Bn), 256>>>(out);
}

// round 2
// speedup vs baseline: 1.0130x; 1.0130x over previous
#include <cuda_runtime.h>
#include <math_constants.h>

// Problem shape (fixed by the dataset)
constexpr int Bn = 4;
constexpr int Tn = 4096;
constexpr int Dn = 1024;
constexpr int Hn = 64;
constexpr float SCALE = 0.125f;  // 1/sqrt(64)

// ---------------- scratch (__device__ globals: the sanctioned scratch path) ----
__device__ float g_Q[(size_t)Bn * Tn * Hn];          // 4 MB
__device__ float g_K[(size_t)Bn * Tn * Hn];          // 4 MB
__device__ float g_V[(size_t)Bn * Tn * Dn];          // 64 MB
__device__ float g_S[(size_t)Bn * Tn * Tn];          // 256 MB raw scaled scores
__device__ float g_m[Bn * Tn];                        // row max
__device__ float g_l[Bn * Tn];                        // row sum-exp

// =============================================================================
// Kernel 1: C[M,N] = A[M,K] * W[N,K]^T   (all row-major). 128x128x8 tile,
// 8x8 per-thread microtile, 256 threads. N may be < BN (guarded).
// =============================================================================
template <int BM, int BN, int BK, int TM, int TN>
__global__ __launch_bounds__(256) void sgemm_tn(const float* __restrict__ A,
                                                const float* __restrict__ W,
                                                float* __restrict__ C,
                                                int M, int N, int K) {
    __shared__ __align__(16) float As[BK][BM];
    __shared__ __align__(16) float Ws[BK][BN];
    const int tid  = threadIdx.x;
    const int bm   = blockIdx.x * BM;
    const int bn   = blockIdx.y * BN;
    const int tcol = tid % (BN / TN);   // 16
    const int trow = tid / (BN / TN);   // 16
    const int a_r  = tid / (BK / 4);    // 0..127
    const int a_c  = (tid % (BK / 4)) * 4;

    const float* Aptr = A + (size_t)(bm + a_r) * K + a_c;
    const float* Wptr = W + (size_t)(bn + a_r) * K + a_c;
    const bool wvalid = (bn + a_r) < N;

    float acc[TM][TN] = {};

    for (int k0 = 0; k0 < K; k0 += BK) {
        float4 av = *(const float4*)(Aptr + k0);
        float4 wv = make_float4(0.f, 0.f, 0.f, 0.f);
        if (wvalid) wv = *(const float4*)(Wptr + k0);
        As[a_c + 0][a_r] = av.x;
        As[a_c + 1][a_r] = av.y;
        As[a_c + 2][a_r] = av.z;
        As[a_c + 3][a_r] = av.w;
        Ws[a_c + 0][a_r] = wv.x;
        Ws[a_c + 1][a_r] = wv.y;
        Ws[a_c + 2][a_r] = wv.z;
        Ws[a_c + 3][a_r] = wv.w;
        __syncthreads();
#pragma unroll
        for (int kk = 0; kk < BK; kk++) {
            float ra[TM], rb[TN];
            *(float4*)&ra[0] = *(const float4*)&As[kk][trow * TM];
            *(float4*)&ra[4] = *(const float4*)&As[kk][trow * TM + 4];
            *(float4*)&rb[0] = *(const float4*)&Ws[kk][tcol * TN];
            *(float4*)&rb[4] = *(const float4*)&Ws[kk][tcol * TN + 4];
#pragma unroll
            for (int i = 0; i < TM; i++)
#pragma unroll
                for (int j = 0; j < TN; j++) acc[i][j] += ra[i] * rb[j];
        }
        __syncthreads();
    }

#pragma unroll
    for (int i = 0; i < TM; i++) {
        const int r = bm + trow * TM + i;
#pragma unroll
        for (int j = 0; j < TN; j += 4) {
            const int c = bn + tcol * TN + j;
            if (c < N) {
                *(float4*)(C + (size_t)r * N + c) =
                    make_float4(acc[i][j], acc[i][j + 1], acc[i][j + 2], acc[i][j + 3]);
            }
        }
    }
}

// =============================================================================
// Kernel 2: raw scaled scores (causal) into g_S + per-row online (m, l).
// One block = (batch, 64-query row tile). 256 threads, 4x4 microtile over a
// 64x64 score tile; sequential loop over key tiles up to the diagonal.
// =============================================================================
__global__ __launch_bounds__(256) void attn_scores_kernel() {
    const int b  = blockIdx.y;
    const int rt = (int)gridDim.x - 1 - (int)blockIdx.x;  // heavy tiles first
    const int i0 = rt * 64;
    const int tid  = threadIdx.x;
    const int tcol = tid & 15;
    const int trow = tid >> 4;

    const float* Qb = g_Q + (size_t)b * Tn * Hn;
    const float* Kb = g_K + (size_t)b * Tn * Hn;
    float*       Sb = g_S + (size_t)b * Tn * Tn;

    __shared__ float Qs[64][Hn + 1];
    __shared__ float Ks[64][Hn + 1];

    // load Q tile (4 threads per row, 16 h each)
    {
        const int r  = tid >> 2;
        const int h0 = (tid & 3) * 16;
        const float* src = Qb + (size_t)(i0 + r) * Hn + h0;
#pragma unroll
        for (int u = 0; u < 4; u++) {
            float4 v = *(const float4*)(src + u * 4);
            Qs[r][h0 + u * 4 + 0] = v.x;
            Qs[r][h0 + u * 4 + 1] = v.y;
            Qs[r][h0 + u * 4 + 2] = v.z;
            Qs[r][h0 + u * 4 + 3] = v.w;
        }
    }

    float run_m[4], run_l[4];
#pragma unroll
    for (int ii = 0; ii < 4; ii++) { run_m[ii] = -CUDART_INF_F; run_l[ii] = 0.f; }

    for (int jt = 0; jt <= rt; jt++) {
        const int j0 = jt * 64;
        __syncthreads();  // Ks safe to overwrite (also covers Qs readiness on iter 0)
        {
            const int r  = tid >> 2;
            const int h0 = (tid & 3) * 16;
            const float* src = Kb + (size_t)(j0 + r) * Hn + h0;
#pragma unroll
            for (int u = 0; u < 4; u++) {
                float4 v = *(const float4*)(src + u * 4);
                Ks[r][h0 + u * 4 + 0] = v.x;
                Ks[r][h0 + u * 4 + 1] = v.y;
                Ks[r][h0 + u * 4 + 2] = v.z;
                Ks[r][h0 + u * 4 + 3] = v.w;
            }
        }
        __syncthreads();

        float s[4][4] = {};
#pragma unroll 8
        for (int h = 0; h < Hn; h++) {
            float qa[4], kb[4];
#pragma unroll
            for (int ii = 0; ii < 4; ii++) qa[ii] = Qs[trow * 4 + ii][h];
#pragma unroll
            for (int jj = 0; jj < 4; jj++) kb[jj] = Ks[tcol * 4 + jj][h];
#pragma unroll
            for (int ii = 0; ii < 4; ii++)
#pragma unroll
                for (int jj = 0; jj < 4; jj++) s[ii][jj] += qa[ii] * kb[jj];
        }

        const bool diag = (jt == rt);
#pragma unroll
        for (int ii = 0; ii < 4; ii++) {
            const int gi = i0 + trow * 4 + ii;
            float v[4];
#pragma unroll
            for (int jj = 0; jj < 4; jj++) {
                const int gj = j0 + tcol * 4 + jj;
                v[jj] = s[ii][jj] * SCALE;
                if (diag && gj > gi) v[jj] = -CUDART_INF_F;
            }
            *(float4*)(Sb + (size_t)gi * Tn + j0 + tcol * 4) =
                make_float4(v[0], v[1], v[2], v[3]);

            // online max / sum-exp across the 16 lanes sharing this row
            float mx = fmaxf(fmaxf(v[0], v[1]), fmaxf(v[2], v[3]));
#pragma unroll
            for (int o = 8; o; o >>= 1)
                mx = fmaxf(mx, __shfl_xor_sync(0xffffffffu, mx, o));
            const float nm = fmaxf(run_m[ii], mx);
            float ps = __expf(v[0] - nm) + __expf(v[1] - nm) +
                       __expf(v[2] - nm) + __expf(v[3] - nm);
#pragma unroll
            for (int o = 8; o; o >>= 1) ps += __shfl_xor_sync(0xffffffffu, ps, o);
            run_l[ii] = run_l[ii] * __expf(run_m[ii] - nm) + ps;
            run_m[ii] = nm;
        }
    }

    if (tcol == 0) {
#pragma unroll
        for (int ii = 0; ii < 4; ii++) {
            const int gi = i0 + trow * 4 + ii;
            g_m[b * Tn + gi] = run_m[ii];
            g_l[b * Tn + gi] = run_l[ii];
        }
    }
}

// =============================================================================
// Kernel 3: O = softmax(S) @ V, normalization applied on the fly while staging
// the S tile into smem. Causal extent per row tile (kEnd = i0+128).
// 128x128x16 tiles, 8x8 microtile, 256 threads.
// =============================================================================
__global__ __launch_bounds__(256) void pv_kernel(float* __restrict__ Out) {
    const int b  = blockIdx.z;
    const int rt = (int)gridDim.x - 1 - (int)blockIdx.x;  // heavy tiles first
    const int i0 = rt * 128;
    const int n0 = blockIdx.y * 128;
    const int tid  = threadIdx.x;
    const int tcol = tid & 15;
    const int trow = tid >> 4;

    const float* Sb = g_S + (size_t)b * Tn * Tn;
    const float* Vb = g_V + (size_t)b * Tn * Dn;
    float*       Ob = Out + (size_t)b * Tn * Dn;

    __shared__ __align__(16) float Ps[16][128];  // [k][m]  (normalized probs)
    __shared__ __align__(16) float Vs[16][128];  // [k][n]
    __shared__ float s_m[128];
    __shared__ float s_li[128];

    if (tid < 128) {
        s_m[tid]  = g_m[b * Tn + i0 + tid];
        s_li[tid] = 1.0f / g_l[b * Tn + i0 + tid];
    }
    __syncthreads();

    float acc[8][8] = {};
    const int kEnd = i0 + 128;

    for (int k0 = 0; k0 < kEnd; k0 += 16) {
        // ---- stage S tile with softmax transform + causal mask ----
#pragma unroll
        for (int t = 0; t < 2; t++) {
            const int idx = tid * 2 + t;
            const int r   = idx >> 2;         // 0..127
            const int c4  = (idx & 3) * 4;    // 0,4,8,12
            const float4 sv = *(const float4*)(Sb + (size_t)(i0 + r) * Tn + k0 + c4);
            const int gi = i0 + r;
            const float mr = s_m[r], lr = s_li[r];
            float p[4];
            p[0] = (k0 + c4 + 0 <= gi) ? __expf(sv.x - mr) * lr : 0.f;
            p[1] = (k0 + c4 + 1 <= gi) ? __expf(sv.y - mr) * lr : 0.f;
            p[2] = (k0 + c4 + 2 <= gi) ? __expf(sv.z - mr) * lr : 0.f;
            p[3] = (k0 + c4 + 3 <= gi) ? __expf(sv.w - mr) * lr : 0.f;
            Ps[c4 + 0][r] = p[0];
            Ps[c4 + 1][r] = p[1];
            Ps[c4 + 2][r] = p[2];
            Ps[c4 + 3][r] = p[3];
        }
        // ---- stage V tile ----
#pragma unroll
        for (int t = 0; t < 2; t++) {
            const int idx = tid + t * 256;
            const int kr  = idx >> 5;
            const int c4  = (idx & 31) * 4;
            *(float4*)&Vs[kr][c4] =
                *(const float4*)(Vb + (size_t)(k0 + kr) * Dn + n0 + c4);
        }
        __syncthreads();

#pragma unroll
        for (int kk = 0; kk < 16; kk++) {
            float ra[8], rb[8];
            *(float4*)&ra[0] = *(const float4*)&Ps[kk][trow * 8];
            *(float4*)&ra[4] = *(const float4*)&Ps[kk][trow * 8 + 4];
            *(float4*)&rb[0] = *(const float4*)&Vs[kk][tcol * 8];
            *(float4*)&rb[4] = *(const float4*)&Vs[kk][tcol * 8 + 4];
#pragma unroll
            for (int i = 0; i < 8; i++)
#pragma unroll
                for (int j = 0; j < 8; j++) acc[i][j] += ra[i] * rb[j];
        }
        __syncthreads();
    }

#pragma unroll
    for (int i = 0; i < 8; i++) {
        const int r = i0 + trow * 8 + i;
        float* dst = Ob + (size_t)r * Dn + n0 + tcol * 8;
        *(float4*)(dst + 0) = make_float4(acc[i][0], acc[i][1], acc[i][2], acc[i][3]);
        *(float4*)(dst + 4) = make_float4(acc[i][4], acc[i][5], acc[i][6], acc[i][7]);
    }
}

// =============================================================================
extern "C" void kernel_launch(void* const* d_in, const int* in_sizes, int n_in,
                              void* d_out, int out_size) {
    const float* x  = (const float*)d_in[0];
    const float* Wk = (const float*)d_in[1];
    const float* Wq = (const float*)d_in[2];
    const float* Wv = (const float*)d_in[3];
    float* out = (float*)d_out;

    void *pQ, *pK, *pV;
    cudaGetSymbolAddress(&pQ, g_Q);
    cudaGetSymbolAddress(&pK, g_K);
    cudaGetSymbolAddress(&pV, g_V);

    const int M = Bn * Tn;  // 16384

    // Projections
    sgemm_tn<128, 128, 8, 8, 8><<<dim3(M / 128, 1), 256>>>(x, Wq, (float*)pQ, M, Hn, Dn);
    sgemm_tn<128, 128, 8, 8, 8><<<dim3(M / 128, 1), 256>>>(x, Wk, (float*)pK, M, Hn, Dn);
    sgemm_tn<128, 128, 8, 8, 8><<<dim3(M / 128, Dn / 128), 256>>>(x, Wv, (float*)pV, M, Dn, Dn);

    // Scores + row stats
    attn_scores_kernel<<<dim3(Tn / 64, Bn), 256>>>();

    // softmax-on-the-fly P @ V
    pv_kernel<<<dim3(Tn / 128, Dn / 128, Bn), 256>>>(out);
}

// round 4
// speedup vs baseline: 1.4000x; 1.3821x over previous
#include <cuda_runtime.h>
#include <math_constants.h>
#include <mma.h>
#include <cstdint>

using namespace nvcuda;

constexpr int Bn = 4, Tn = 4096, Dn = 1024, Hn = 64;
constexpr int Mt = Bn * Tn;              // 16384 tokens
constexpr float SCALE = 0.125f;          // 1/sqrt(64)

// ----------------------------- scratch --------------------------------------
__device__ float g_Q[(size_t)Mt * Hn];           // Q (near-fp32, 3xTF32 product)
__device__ float g_K[(size_t)Mt * Hn];           // K
__device__ float g_V[(size_t)Mt * Dn];           // V, natural [token][e]
__device__ float g_S[(size_t)Bn * Tn * Tn];      // raw scores -> normalized P

// ----------------------------- wmma types -----------------------------------
using FragA  = wmma::fragment<wmma::matrix_a, 16, 16, 8, wmma::precision::tf32, wmma::row_major>;
using FragBc = wmma::fragment<wmma::matrix_b, 16, 16, 8, wmma::precision::tf32, wmma::col_major>;
using FragBr = wmma::fragment<wmma::matrix_b, 16, 16, 8, wmma::precision::tf32, wmma::row_major>;
using FragC  = wmma::fragment<wmma::accumulator, 16, 16, 8, float>;

template <class F>
__device__ __forceinline__ void round_frag(F& x) {
#pragma unroll
    for (int i = 0; i < x.num_elements; ++i) x.x[i] = wmma::__float_to_tf32(x.x[i]);
}
template <class F>
__device__ __forceinline__ void split_frag(const F& x, F& hi, F& lo) {
#pragma unroll
    for (int i = 0; i < x.num_elements; ++i) {
        float h = wmma::__float_to_tf32(x.x[i]);
        hi.x[i] = h;
        lo.x[i] = wmma::__float_to_tf32(x.x[i] - h);
    }
}

// =============================================================================
// Kernel 1: fused Q+K projection, 3xTF32. C[128 x 128] = x_tile * [Wq;Wk]^T
// 256 thr, warp grid 2x4 (warp tile 64x32), K staged in chunks of 32.
// =============================================================================
__global__ __launch_bounds__(256) void proj_qk(const float* __restrict__ x,
                                               const float* __restrict__ Wq,
                                               const float* __restrict__ Wk) {
    __shared__ float As[128][36];
    __shared__ float Bs[128][36];
    const int tid = threadIdx.x, wid = tid >> 5;
    const int bm = blockIdx.x * 128;
    const int wm = (wid >> 2) * 64, wn = (wid & 3) * 32;

    FragC acc[4][2];
#pragma unroll
    for (int i = 0; i < 4; ++i)
#pragma unroll
        for (int j = 0; j < 2; ++j) wmma::fill_fragment(acc[i][j], 0.0f);

    for (int k0 = 0; k0 < Dn; k0 += 32) {
#pragma unroll
        for (int t = 0; t < 4; ++t) {
            const int idx = tid + t * 256, r = idx >> 3, c = (idx & 7) * 4;
            float4 v = *(const float4*)(x + (size_t)(bm + r) * Dn + k0 + c);
            As[r][c] = v.x; As[r][c + 1] = v.y; As[r][c + 2] = v.z; As[r][c + 3] = v.w;
            const float* wsrc = (r < 64) ? (Wq + (size_t)r * Dn) : (Wk + (size_t)(r - 64) * Dn);
            float4 w = *(const float4*)(wsrc + k0 + c);
            Bs[r][c] = w.x; Bs[r][c + 1] = w.y; Bs[r][c + 2] = w.z; Bs[r][c + 3] = w.w;
        }
        __syncthreads();
#pragma unroll
        for (int kk = 0; kk < 4; ++kk) {
            FragA ah[4], al[4];
            FragBc bh[2], bl[2];
#pragma unroll
            for (int i = 0; i < 4; ++i) {
                FragA a;
                wmma::load_matrix_sync(a, &As[wm + i * 16][kk * 8], 36);
                split_frag(a, ah[i], al[i]);
            }
#pragma unroll
            for (int j = 0; j < 2; ++j) {
                FragBc b;
                wmma::load_matrix_sync(b, &Bs[wn + j * 16][kk * 8], 36);
                split_frag(b, bh[j], bl[j]);
            }
#pragma unroll
            for (int i = 0; i < 4; ++i)
#pragma unroll
                for (int j = 0; j < 2; ++j) {
                    wmma::mma_sync(acc[i][j], ah[i], bh[j], acc[i][j]);
                    wmma::mma_sync(acc[i][j], ah[i], bl[j], acc[i][j]);
                    wmma::mma_sync(acc[i][j], al[i], bh[j], acc[i][j]);
                }
        }
        __syncthreads();
    }
#pragma unroll
    for (int i = 0; i < 4; ++i)
#pragma unroll
        for (int j = 0; j < 2; ++j) {
            const int row = bm + wm + i * 16;
            const int col = wn + j * 16;
            float* dst = (col < 64) ? (g_Q + (size_t)row * Hn + col)
                                    : (g_K + (size_t)row * Hn + (col - 64));
            wmma::store_matrix_sync(dst, acc[i][j], Hn, wmma::mem_row_major);
        }
}

// =============================================================================
// Kernel 2: V projection, plain tf32. C[128 x 128] tile of g_V = x * Wv^T
// =============================================================================
__global__ __launch_bounds__(256) void proj_v(const float* __restrict__ x,
                                              const float* __restrict__ Wv) {
    __shared__ float As[128][36];
    __shared__ float Bs[128][36];
    const int tid = threadIdx.x, wid = tid >> 5;
    const int bm = blockIdx.x * 128;
    const int e0 = blockIdx.y * 128;
    const int wm = (wid >> 2) * 64, wn = (wid & 3) * 32;

    FragC acc[4][2];
#pragma unroll
    for (int i = 0; i < 4; ++i)
#pragma unroll
        for (int j = 0; j < 2; ++j) wmma::fill_fragment(acc[i][j], 0.0f);

    for (int k0 = 0; k0 < Dn; k0 += 32) {
#pragma unroll
        for (int t = 0; t < 4; ++t) {
            const int idx = tid + t * 256, r = idx >> 3, c = (idx & 7) * 4;
            float4 v = *(const float4*)(x + (size_t)(bm + r) * Dn + k0 + c);
            As[r][c] = v.x; As[r][c + 1] = v.y; As[r][c + 2] = v.z; As[r][c + 3] = v.w;
            float4 w = *(const float4*)(Wv + (size_t)(e0 + r) * Dn + k0 + c);
            Bs[r][c] = w.x; Bs[r][c + 1] = w.y; Bs[r][c + 2] = w.z; Bs[r][c + 3] = w.w;
        }
        __syncthreads();
#pragma unroll
        for (int kk = 0; kk < 4; ++kk) {
            FragA a[4];
            FragBc b[2];
#pragma unroll
            for (int i = 0; i < 4; ++i) {
                wmma::load_matrix_sync(a[i], &As[wm + i * 16][kk * 8], 36);
                round_frag(a[i]);
            }
#pragma unroll
            for (int j = 0; j < 2; ++j) {
                wmma::load_matrix_sync(b[j], &Bs[wn + j * 16][kk * 8], 36);
                round_frag(b[j]);
            }
#pragma unroll
            for (int i = 0; i < 4; ++i)
#pragma unroll
                for (int j = 0; j < 2; ++j)
                    wmma::mma_sync(acc[i][j], a[i], b[j], acc[i][j]);
        }
        __syncthreads();
    }
#pragma unroll
    for (int i = 0; i < 4; ++i)
#pragma unroll
        for (int j = 0; j < 2; ++j)
            wmma::store_matrix_sync(g_V + (size_t)(bm + wm + i * 16) * Dn + e0 + wn + j * 16,
                                    acc[i][j], Dn, wmma::mem_row_major);
}

// =============================================================================
// Kernel 3: scores, 3xTF32, SCALE folded into Q. One CTA per (rt, jt<=rt, b)
// tile pair: S[128 x 128] = (SCALE*Q_rt) * K_jt^T, stored RAW to g_S.
// =============================================================================
__global__ __launch_bounds__(256) void scores_k() {
    extern __shared__ float dynf[];
    float (*Qs)[68] = (float(*)[68])dynf;               // 128 x 68
    float (*Ks)[68] = (float(*)[68])(dynf + 128 * 68);  // 128 x 68

    const int tid = threadIdx.x, wid = tid >> 5;
    const int b = blockIdx.y;
    // decode triangular pair index -> (rt, jt)
    int idx = blockIdx.x;
    int rt = (int)((sqrtf(8.0f * idx + 1.0f) - 1.0f) * 0.5f);
    while ((rt + 1) * (rt + 2) / 2 <= idx) ++rt;
    while (rt * (rt + 1) / 2 > idx) --rt;
    const int jt = idx - rt * (rt + 1) / 2;
    const int i0 = rt * 128, j0 = jt * 128;
    const int wm = (wid >> 2) * 64, wn = (wid & 3) * 32;

    const float* Qb = g_Q + (size_t)(b * Tn + i0) * Hn;
    const float* Kb = g_K + (size_t)(b * Tn + j0) * Hn;
    float* Sb = g_S + (size_t)b * Tn * Tn;

    // stage Q (scaled) and K tiles: 128 x 64 each
#pragma unroll
    for (int t = 0; t < 8; ++t) {
        const int id2 = tid + t * 256, r = id2 >> 4, c = (id2 & 15) * 4;
        float4 q = *(const float4*)(Qb + (size_t)r * Hn + c);
        Qs[r][c] = q.x * SCALE; Qs[r][c + 1] = q.y * SCALE;
        Qs[r][c + 2] = q.z * SCALE; Qs[r][c + 3] = q.w * SCALE;
        float4 k = *(const float4*)(Kb + (size_t)r * Hn + c);
        Ks[r][c] = k.x; Ks[r][c + 1] = k.y; Ks[r][c + 2] = k.z; Ks[r][c + 3] = k.w;
    }
    __syncthreads();

    FragC acc[4][2];
#pragma unroll
    for (int i = 0; i < 4; ++i)
#pragma unroll
        for (int j = 0; j < 2; ++j) wmma::fill_fragment(acc[i][j], 0.0f);

#pragma unroll
    for (int kk = 0; kk < 8; ++kk) {
        FragA ah[4], al[4];
        FragBc bh[2], bl[2];
#pragma unroll
        for (int i = 0; i < 4; ++i) {
            FragA a;
            wmma::load_matrix_sync(a, &Qs[wm + i * 16][kk * 8], 68);
            split_frag(a, ah[i], al[i]);
        }
#pragma unroll
        for (int j = 0; j < 2; ++j) {
            FragBc bb;
            wmma::load_matrix_sync(bb, &Ks[wn + j * 16][kk * 8], 68);
            split_frag(bb, bh[j], bl[j]);
        }
#pragma unroll
        for (int i = 0; i < 4; ++i)
#pragma unroll
            for (int j = 0; j < 2; ++j) {
                wmma::mma_sync(acc[i][j], ah[i], bh[j], acc[i][j]);
                wmma::mma_sync(acc[i][j], ah[i], bl[j], acc[i][j]);
                wmma::mma_sync(acc[i][j], al[i], bh[j], acc[i][j]);
            }
    }
#pragma unroll
    for (int i = 0; i < 4; ++i)
#pragma unroll
        for (int j = 0; j < 2; ++j)
            wmma::store_matrix_sync(Sb + (size_t)(i0 + wm + i * 16) * Tn + j0 + wn + j * 16,
                                    acc[i][j], Tn, wmma::mem_row_major);
}

// =============================================================================
// Kernel 4: per-row softmax stats + in-place normalize S -> P (masked, zero
// beyond the diagonal up to the 128-tile boundary). 2 threads per row.
// =============================================================================
__global__ __launch_bounds__(256) void stats_k() {
    const int b = blockIdx.y;
    const int i0 = blockIdx.x * 128;
    const int t = threadIdx.x, r = t >> 1, h = t & 1;
    const int gi = i0 + r;
    float* S = g_S + ((size_t)b * Tn + gi) * Tn;
    const int len = gi + 1;
    const int tileEnd = i0 + 128;

    float rm = -CUDART_INF_F, rl = 0.f;
    for (int j0 = h * 64; j0 < len; j0 += 128) {
        float v[64];
#pragma unroll
        for (int q = 0; q < 16; ++q) {
            float4 s = *(const float4*)(S + j0 + q * 4);
            v[q * 4] = s.x; v[q * 4 + 1] = s.y; v[q * 4 + 2] = s.z; v[q * 4 + 3] = s.w;
        }
        float mx = -CUDART_INF_F;
#pragma unroll
        for (int j = 0; j < 64; ++j)
            if (j0 + j < len) mx = fmaxf(mx, v[j]);
        const float nm = fmaxf(rm, mx);
        float se = 0.f;
#pragma unroll
        for (int j = 0; j < 64; ++j)
            if (j0 + j < len) se += __expf(v[j] - nm);
        rl = rl * __expf(rm - nm) + se;
        rm = nm;
    }
    // merge the pair (lanes 2r, 2r+1 are adjacent in a warp)
    const float om = __shfl_xor_sync(0xffffffffu, rm, 1);
    const float ol = __shfl_xor_sync(0xffffffffu, rl, 1);
    const float nm = fmaxf(rm, om);
    const float l = rl * __expf(rm - nm) + ol * __expf(om - nm);
    const float inv = 1.0f / l;

    for (int j0 = h * 64; j0 < tileEnd; j0 += 128) {
#pragma unroll
        for (int q = 0; q < 16; ++q) {
            const int jb = j0 + q * 4;
            float4 s = *(const float4*)(S + jb);
            float4 p;
            p.x = (jb + 0 < len) ? __expf(s.x - nm) * inv : 0.f;
            p.y = (jb + 1 < len) ? __expf(s.y - nm) * inv : 0.f;
            p.z = (jb + 2 < len) ? __expf(s.z - nm) * inv : 0.f;
            p.w = (jb + 3 < len) ? __expf(s.w - nm) * inv : 0.f;
            *(float4*)(S + jb) = p;
        }
    }
}

// =============================================================================
// Kernel 5: O = P @ V, plain tf32, everything straight from global (L2-hot).
// Per CTA: 128 rows x 128 e-cols; k extent = (rt+1)*128 (causal).
// =============================================================================
__global__ __launch_bounds__(256) void pv_k(float* __restrict__ Out) {
    const int tid = threadIdx.x, wid = tid >> 5;
    const int b = blockIdx.z;
    const int rt = (int)gridDim.x - 1 - (int)blockIdx.x;   // heavy first
    const int i0 = rt * 128;
    const int e0 = blockIdx.y * 128;
    const int wm = (wid >> 2) * 64, wn = (wid & 3) * 32;

    const float* Pb = g_S + (size_t)b * Tn * Tn + (size_t)i0 * Tn;
    const float* Vb = g_V + (size_t)b * Tn * Dn;

    FragC acc[4][2];
#pragma unroll
    for (int i = 0; i < 4; ++i)
#pragma unroll
        for (int j = 0; j < 2; ++j) wmma::fill_fragment(acc[i][j], 0.0f);

    const int kEnd = (rt + 1) * 128;
    for (int k0 = 0; k0 < kEnd; k0 += 32) {
#pragma unroll
        for (int kk = 0; kk < 4; ++kk) {
            FragA a[4];
            FragBr bfr[2];
#pragma unroll
            for (int i = 0; i < 4; ++i) {
                wmma::load_matrix_sync(a[i], Pb + (size_t)(wm + i * 16) * Tn + k0 + kk * 8, Tn);
                round_frag(a[i]);
            }
#pragma unroll
            for (int j = 0; j < 2; ++j) {
                wmma::load_matrix_sync(bfr[j],
                                       Vb + (size_t)(k0 + kk * 8) * Dn + e0 + wn + j * 16, Dn);
                round_frag(bfr[j]);
            }
#pragma unroll
            for (int i = 0; i < 4; ++i)
#pragma unroll
                for (int j = 0; j < 2; ++j)
                    wmma::mma_sync(acc[i][j], a[i], bfr[j], acc[i][j]);
        }
    }
#pragma unroll
    for (int i = 0; i < 4; ++i)
#pragma unroll
        for (int j = 0; j < 2; ++j)
            wmma::store_matrix_sync(Out + (size_t)(b * Tn + i0 + wm + i * 16) * Dn + e0 + wn + j * 16,
                                    acc[i][j], Dn, wmma::mem_row_major);
}

// =============================================================================
extern "C" void kernel_launch(void* const* d_in, const int* in_sizes, int n_in,
                              void* d_out, int out_size) {
    const float* x  = (const float*)d_in[0];
    const float* Wk = (const float*)d_in[1];
    const float* Wq = (const float*)d_in[2];
    const float* Wv = (const float*)d_in[3];
    float* out = (float*)d_out;

    const int SM_SCORES = 2 * 128 * 68 * 4;   // 69632 B
    cudaFuncSetAttribute(scores_k, cudaFuncAttributeMaxDynamicSharedMemorySize, SM_SCORES);

    proj_qk<<<Mt / 128, 256>>>(x, Wq, Wk);
    proj_v<<<dim3(Mt / 128, Dn / 128), 256>>>(x, Wv);

    const int npairs = (Tn / 128) * (Tn / 128 + 1) / 2;   // 528
    scores_k<<<dim3(npairs, Bn), 256, SM_SCORES>>>();

    stats_k<<<dim3(Tn / 128, Bn), 256>>>();

    pv_k<<<dim3(Tn / 128, Dn / 128, Bn), 256>>>(out);
}

// round 5
// speedup vs baseline: 1.9463x; 1.3902x over previous
#include <cuda_runtime.h>
#include <math_constants.h>
#include <mma.h>
#include <cstdint>

using namespace nvcuda;

constexpr int Bn = 4, Tn = 4096, Dn = 1024, Hn = 64;
constexpr int Mt = Bn * Tn;              // 16384 tokens
constexpr float SCALE = 0.125f;          // 1/sqrt(64)

// ----------------------------- scratch --------------------------------------
__device__ float g_Q[(size_t)Mt * Hn];           // Q (near-fp32, 3xTF32 product)
__device__ float g_K[(size_t)Mt * Hn];           // K
__device__ float g_V[(size_t)Mt * Dn];           // V, natural [token][e]
__device__ float g_S[(size_t)Bn * Tn * Tn];      // raw scores -> normalized P

// ----------------------------- wmma types -----------------------------------
using FragA  = wmma::fragment<wmma::matrix_a, 16, 16, 8, wmma::precision::tf32, wmma::row_major>;
using FragBc = wmma::fragment<wmma::matrix_b, 16, 16, 8, wmma::precision::tf32, wmma::col_major>;
using FragBr = wmma::fragment<wmma::matrix_b, 16, 16, 8, wmma::precision::tf32, wmma::row_major>;
using FragC  = wmma::fragment<wmma::accumulator, 16, 16, 8, float>;

template <class F>
__device__ __forceinline__ void round_frag(F& x) {
#pragma unroll
    for (int i = 0; i < x.num_elements; ++i) x.x[i] = wmma::__float_to_tf32(x.x[i]);
}
template <class F>
__device__ __forceinline__ void split_frag(const F& x, F& hi, F& lo) {
#pragma unroll
    for (int i = 0; i < x.num_elements; ++i) {
        float h = wmma::__float_to_tf32(x.x[i]);
        hi.x[i] = h;
        lo.x[i] = wmma::__float_to_tf32(x.x[i] - h);
    }
}

// =============================================================================
// Kernel 1: fused Q+K projection, 3xTF32. C[128 x 128] = x_tile * [Wq;Wk]^T
// =============================================================================
__global__ __launch_bounds__(256) void proj_qk(const float* __restrict__ x,
                                               const float* __restrict__ Wq,
                                               const float* __restrict__ Wk) {
    __shared__ float As[128][36];
    __shared__ float Bs[128][36];
    const int tid = threadIdx.x, wid = tid >> 5;
    const int bm = blockIdx.x * 128;
    const int wm = (wid >> 2) * 64, wn = (wid & 3) * 32;

    FragC acc[4][2];
#pragma unroll
    for (int i = 0; i < 4; ++i)
#pragma unroll
        for (int j = 0; j < 2; ++j) wmma::fill_fragment(acc[i][j], 0.0f);

    for (int k0 = 0; k0 < Dn; k0 += 32) {
#pragma unroll
        for (int t = 0; t < 4; ++t) {
            const int idx = tid + t * 256, r = idx >> 3, c = (idx & 7) * 4;
            float4 v = *(const float4*)(x + (size_t)(bm + r) * Dn + k0 + c);
            As[r][c] = v.x; As[r][c + 1] = v.y; As[r][c + 2] = v.z; As[r][c + 3] = v.w;
            const float* wsrc = (r < 64) ? (Wq + (size_t)r * Dn) : (Wk + (size_t)(r - 64) * Dn);
            float4 w = *(const float4*)(wsrc + k0 + c);
            Bs[r][c] = w.x; Bs[r][c + 1] = w.y; Bs[r][c + 2] = w.z; Bs[r][c + 3] = w.w;
        }
        __syncthreads();
#pragma unroll
        for (int kk = 0; kk < 4; ++kk) {
            FragA ah[4], al[4];
            FragBc bh[2], bl[2];
#pragma unroll
            for (int i = 0; i < 4; ++i) {
                FragA a;
                wmma::load_matrix_sync(a, &As[wm + i * 16][kk * 8], 36);
                split_frag(a, ah[i], al[i]);
            }
#pragma unroll
            for (int j = 0; j < 2; ++j) {
                FragBc b;
                wmma::load_matrix_sync(b, &Bs[wn + j * 16][kk * 8], 36);
                split_frag(b, bh[j], bl[j]);
            }
#pragma unroll
            for (int i = 0; i < 4; ++i)
#pragma unroll
                for (int j = 0; j < 2; ++j) {
                    wmma::mma_sync(acc[i][j], ah[i], bh[j], acc[i][j]);
                    wmma::mma_sync(acc[i][j], ah[i], bl[j], acc[i][j]);
                    wmma::mma_sync(acc[i][j], al[i], bh[j], acc[i][j]);
                }
        }
        __syncthreads();
    }
#pragma unroll
    for (int i = 0; i < 4; ++i)
#pragma unroll
        for (int j = 0; j < 2; ++j) {
            const int row = bm + wm + i * 16;
            const int col = wn + j * 16;
            float* dst = (col < 64) ? (g_Q + (size_t)row * Hn + col)
                                    : (g_K + (size_t)row * Hn + (col - 64));
            wmma::store_matrix_sync(dst, acc[i][j], Hn, wmma::mem_row_major);
        }
}

// =============================================================================
// Kernel 2: V projection, plain tf32. C[128 x 128] tile of g_V = x * Wv^T
// =============================================================================
__global__ __launch_bounds__(256) void proj_v(const float* __restrict__ x,
                                              const float* __restrict__ Wv) {
    __shared__ float As[128][36];
    __shared__ float Bs[128][36];
    const int tid = threadIdx.x, wid = tid >> 5;
    const int bm = blockIdx.x * 128;
    const int e0 = blockIdx.y * 128;
    const int wm = (wid >> 2) * 64, wn = (wid & 3) * 32;

    FragC acc[4][2];
#pragma unroll
    for (int i = 0; i < 4; ++i)
#pragma unroll
        for (int j = 0; j < 2; ++j) wmma::fill_fragment(acc[i][j], 0.0f);

    for (int k0 = 0; k0 < Dn; k0 += 32) {
#pragma unroll
        for (int t = 0; t < 4; ++t) {
            const int idx = tid + t * 256, r = idx >> 3, c = (idx & 7) * 4;
            float4 v = *(const float4*)(x + (size_t)(bm + r) * Dn + k0 + c);
            As[r][c] = wmma::__float_to_tf32(v.x);
            As[r][c + 1] = wmma::__float_to_tf32(v.y);
            As[r][c + 2] = wmma::__float_to_tf32(v.z);
            As[r][c + 3] = wmma::__float_to_tf32(v.w);
            float4 w = *(const float4*)(Wv + (size_t)(e0 + r) * Dn + k0 + c);
            Bs[r][c] = wmma::__float_to_tf32(w.x);
            Bs[r][c + 1] = wmma::__float_to_tf32(w.y);
            Bs[r][c + 2] = wmma::__float_to_tf32(w.z);
            Bs[r][c + 3] = wmma::__float_to_tf32(w.w);
        }
        __syncthreads();
#pragma unroll
        for (int kk = 0; kk < 4; ++kk) {
            FragA a[4];
            FragBc b[2];
#pragma unroll
            for (int i = 0; i < 4; ++i)
                wmma::load_matrix_sync(a[i], &As[wm + i * 16][kk * 8], 36);
#pragma unroll
            for (int j = 0; j < 2; ++j)
                wmma::load_matrix_sync(b[j], &Bs[wn + j * 16][kk * 8], 36);
#pragma unroll
            for (int i = 0; i < 4; ++i)
#pragma unroll
                for (int j = 0; j < 2; ++j)
                    wmma::mma_sync(acc[i][j], a[i], b[j], acc[i][j]);
        }
        __syncthreads();
    }
#pragma unroll
    for (int i = 0; i < 4; ++i)
#pragma unroll
        for (int j = 0; j < 2; ++j)
            wmma::store_matrix_sync(g_V + (size_t)(bm + wm + i * 16) * Dn + e0 + wn + j * 16,
                                    acc[i][j], Dn, wmma::mem_row_major);
}

// =============================================================================
// Kernel 3: scores, 3xTF32, SCALE folded into Q. One CTA per (rt, jt<=rt, b).
// =============================================================================
__global__ __launch_bounds__(256) void scores_k() {
    extern __shared__ float dynf[];
    float (*Qs)[68] = (float(*)[68])dynf;               // 128 x 68
    float (*Ks)[68] = (float(*)[68])(dynf + 128 * 68);  // 128 x 68

    const int tid = threadIdx.x, wid = tid >> 5;
    const int b = blockIdx.y;
    int idx = blockIdx.x;
    int rt = (int)((sqrtf(8.0f * idx + 1.0f) - 1.0f) * 0.5f);
    while ((rt + 1) * (rt + 2) / 2 <= idx) ++rt;
    while (rt * (rt + 1) / 2 > idx) --rt;
    const int jt = idx - rt * (rt + 1) / 2;
    const int i0 = rt * 128, j0 = jt * 128;
    const int wm = (wid >> 2) * 64, wn = (wid & 3) * 32;

    const float* Qb = g_Q + (size_t)(b * Tn + i0) * Hn;
    const float* Kb = g_K + (size_t)(b * Tn + j0) * Hn;
    float* Sb = g_S + (size_t)b * Tn * Tn;

#pragma unroll
    for (int t = 0; t < 8; ++t) {
        const int id2 = tid + t * 256, r = id2 >> 4, c = (id2 & 15) * 4;
        float4 q = *(const float4*)(Qb + (size_t)r * Hn + c);
        Qs[r][c] = q.x * SCALE; Qs[r][c + 1] = q.y * SCALE;
        Qs[r][c + 2] = q.z * SCALE; Qs[r][c + 3] = q.w * SCALE;
        float4 k = *(const float4*)(Kb + (size_t)r * Hn + c);
        Ks[r][c] = k.x; Ks[r][c + 1] = k.y; Ks[r][c + 2] = k.z; Ks[r][c + 3] = k.w;
    }
    __syncthreads();

    FragC acc[4][2];
#pragma unroll
    for (int i = 0; i < 4; ++i)
#pragma unroll
        for (int j = 0; j < 2; ++j) wmma::fill_fragment(acc[i][j], 0.0f);

#pragma unroll
    for (int kk = 0; kk < 8; ++kk) {
        FragA ah[4], al[4];
        FragBc bh[2], bl[2];
#pragma unroll
        for (int i = 0; i < 4; ++i) {
            FragA a;
            wmma::load_matrix_sync(a, &Qs[wm + i * 16][kk * 8], 68);
            split_frag(a, ah[i], al[i]);
        }
#pragma unroll
        for (int j = 0; j < 2; ++j) {
            FragBc bb;
            wmma::load_matrix_sync(bb, &Ks[wn + j * 16][kk * 8], 68);
            split_frag(bb, bh[j], bl[j]);
        }
#pragma unroll
        for (int i = 0; i < 4; ++i)
#pragma unroll
            for (int j = 0; j < 2; ++j) {
                wmma::mma_sync(acc[i][j], ah[i], bh[j], acc[i][j]);
                wmma::mma_sync(acc[i][j], ah[i], bl[j], acc[i][j]);
                wmma::mma_sync(acc[i][j], al[i], bh[j], acc[i][j]);
            }
    }
#pragma unroll
    for (int i = 0; i < 4; ++i)
#pragma unroll
        for (int j = 0; j < 2; ++j)
            wmma::store_matrix_sync(Sb + (size_t)(i0 + wm + i * 16) * Tn + j0 + wn + j * 16,
                                    acc[i][j], Tn, wmma::mem_row_major);
}

// =============================================================================
// Kernel 4: warp-per-row softmax stats + in-place normalize S -> P.
// Online (m,l) per lane, butterfly merge with -inf guards; no register buffer.
// =============================================================================
__global__ __launch_bounds__(256) void stats_k() {
    const int b = blockIdx.y;
    const int wid = threadIdx.x >> 5, lane = threadIdx.x & 31;
    const int gi = blockIdx.x * 8 + wid;
    float* S = g_S + ((size_t)b * Tn + gi) * Tn;
    const int len = gi + 1;
    const int tileEnd = (gi & ~127) + 128;

    float rm = -CUDART_INF_F, rl = 0.f;
    for (int j0 = lane * 4; j0 < len; j0 += 128) {
        float4 s = *(const float4*)(S + j0);
        float v0 = (j0 + 0 < len) ? s.x : -CUDART_INF_F;
        float v1 = (j0 + 1 < len) ? s.y : -CUDART_INF_F;
        float v2 = (j0 + 2 < len) ? s.z : -CUDART_INF_F;
        float v3 = (j0 + 3 < len) ? s.w : -CUDART_INF_F;
        const float mx = fmaxf(fmaxf(v0, v1), fmaxf(v2, v3));
        if (mx > -CUDART_INF_F) {
            const float nm = fmaxf(rm, mx);
            const float keep = (rm > -CUDART_INF_F) ? rl * __expf(rm - nm) : 0.f;
            rl = keep + __expf(v0 - nm) + __expf(v1 - nm) +
                 __expf(v2 - nm) + __expf(v3 - nm);
            rm = nm;
        }
    }
#pragma unroll
    for (int o = 16; o; o >>= 1) {
        const float om = __shfl_xor_sync(0xffffffffu, rm, o);
        const float ol = __shfl_xor_sync(0xffffffffu, rl, o);
        const float nm = fmaxf(rm, om);
        const float a = (rm > -CUDART_INF_F) ? rl * __expf(rm - nm) : 0.f;
        const float c = (om > -CUDART_INF_F) ? ol * __expf(om - nm) : 0.f;
        rl = a + c;
        rm = nm;
    }
    const float inv = 1.0f / rl;

    for (int j0 = lane * 4; j0 < tileEnd; j0 += 128) {
        float4 s = *(const float4*)(S + j0);
        float4 p;
        p.x = (j0 + 0 < len) ? __expf(s.x - rm) * inv : 0.f;
        p.y = (j0 + 1 < len) ? __expf(s.y - rm) * inv : 0.f;
        p.z = (j0 + 2 < len) ? __expf(s.z - rm) * inv : 0.f;
        p.w = (j0 + 3 < len) ? __expf(s.w - rm) * inv : 0.f;
        *(float4*)(S + j0) = p;
    }
}

// =============================================================================
// Kernel 5: O = P @ V, plain tf32, smem-staged (coalesced), k-chunk 32.
// Per CTA: 128 rows x 128 e-cols; k extent = (rt+1)*128 (causal, heavy first).
// =============================================================================
__global__ __launch_bounds__(256, 2) void pv_k(float* __restrict__ Out) {
    __shared__ float Ps[128][36];   // [m][k]
    __shared__ float Vs[32][132];   // [k][n]
    const int tid = threadIdx.x, wid = tid >> 5;
    const int b = blockIdx.z;
    const int rt = (int)gridDim.x - 1 - (int)blockIdx.x;   // heavy first
    const int i0 = rt * 128;
    const int e0 = blockIdx.y * 128;
    const int wm = (wid >> 2) * 64, wn = (wid & 3) * 32;

    const float* Pb = g_S + (size_t)b * Tn * Tn + (size_t)i0 * Tn;
    const float* Vb = g_V + (size_t)b * Tn * Dn;

    FragC acc[4][2];
#pragma unroll
    for (int i = 0; i < 4; ++i)
#pragma unroll
        for (int j = 0; j < 2; ++j) wmma::fill_fragment(acc[i][j], 0.0f);

    const int kEnd = (rt + 1) * 128;
    for (int k0 = 0; k0 < kEnd; k0 += 32) {
        // stage P 128x32 (pre-rounded to tf32)
#pragma unroll
        for (int t = 0; t < 2; ++t) {
            const int idx = tid + t * 256, r = idx >> 2, c = (idx & 3) * 8;
            float4 p0 = *(const float4*)(Pb + (size_t)r * Tn + k0 + c);
            float4 p1 = *(const float4*)(Pb + (size_t)r * Tn + k0 + c + 4);
            Ps[r][c + 0] = wmma::__float_to_tf32(p0.x);
            Ps[r][c + 1] = wmma::__float_to_tf32(p0.y);
            Ps[r][c + 2] = wmma::__float_to_tf32(p0.z);
            Ps[r][c + 3] = wmma::__float_to_tf32(p0.w);
            Ps[r][c + 4] = wmma::__float_to_tf32(p1.x);
            Ps[r][c + 5] = wmma::__float_to_tf32(p1.y);
            Ps[r][c + 6] = wmma::__float_to_tf32(p1.z);
            Ps[r][c + 7] = wmma::__float_to_tf32(p1.w);
        }
        // stage V 32x128 (pre-rounded to tf32)
#pragma unroll
        for (int t = 0; t < 4; ++t) {
            const int idx = tid + t * 256, r = idx >> 5, c = (idx & 31) * 4;
            float4 v = *(const float4*)(Vb + (size_t)(k0 + r) * Dn + e0 + c);
            Vs[r][c + 0] = wmma::__float_to_tf32(v.x);
            Vs[r][c + 1] = wmma::__float_to_tf32(v.y);
            Vs[r][c + 2] = wmma::__float_to_tf32(v.z);
            Vs[r][c + 3] = wmma::__float_to_tf32(v.w);
        }
        __syncthreads();
#pragma unroll
        for (int kk = 0; kk < 4; ++kk) {
            FragA a[4];
            FragBr bfr[2];
#pragma unroll
            for (int i = 0; i < 4; ++i)
                wmma::load_matrix_sync(a[i], &Ps[wm + i * 16][kk * 8], 36);
#pragma unroll
            for (int j = 0; j < 2; ++j)
                wmma::load_matrix_sync(bfr[j], &Vs[kk * 8][wn + j * 16], 132);
#pragma unroll
            for (int i = 0; i < 4; ++i)
#pragma unroll
                for (int j = 0; j < 2; ++j)
                    wmma::mma_sync(acc[i][j], a[i], bfr[j], acc[i][j]);
        }
        __syncthreads();
    }
#pragma unroll
    for (int i = 0; i < 4; ++i)
#pragma unroll
        for (int j = 0; j < 2; ++j)
            wmma::store_matrix_sync(Out + (size_t)(b * Tn + i0 + wm + i * 16) * Dn + e0 + wn + j * 16,
                                    acc[i][j], Dn, wmma::mem_row_major);
}

// =============================================================================
extern "C" void kernel_launch(void* const* d_in, const int* in_sizes, int n_in,
                              void* d_out, int out_size) {
    const float* x  = (const float*)d_in[0];
    const float* Wk = (const float*)d_in[1];
    const float* Wq = (const float*)d_in[2];
    const float* Wv = (const float*)d_in[3];
    float* out = (float*)d_out;

    const int SM_SCORES = 2 * 128 * 68 * 4;   // 69632 B
    cudaFuncSetAttribute(scores_k, cudaFuncAttributeMaxDynamicSharedMemorySize, SM_SCORES);

    proj_qk<<<Mt / 128, 256>>>(x, Wq, Wk);
    proj_v<<<dim3(Mt / 128, Dn / 128), 256>>>(x, Wv);

    const int npairs = (Tn / 128) * (Tn / 128 + 1) / 2;   // 528
    scores_k<<<dim3(npairs, Bn), 256, SM_SCORES>>>();

    stats_k<<<dim3(Tn / 8, Bn), 256>>>();

    pv_k<<<dim3(Tn / 128, Dn / 128, Bn), 256>>>(out);
}